// round 16
// baseline (speedup 1.0000x reference)
#include <cuda_runtime.h>
#include <cuda_fp16.h>
#include <cstdint>

#define B_SZ 8192
#define D_SZ 512
#define U_SZ 512
#define M_SZ 16

// ---------------------------------------------------------------------------
// Scratch (static __device__ — no allocations allowed)
// ---------------------------------------------------------------------------
__device__ float  g_sim[B_SZ * M_SZ];          // sim/16
__device__ __half g_xh[B_SZ * D_SZ];           // [b][d]
__device__ __half g_wh[M_SZ * U_SZ * D_SZ];    // [m][u][d]  (k-major B)
__device__ __half g_kkh[512 * 72];             // key_kernel fp16, padded [512][72]
__device__ int    g_simflag;                   // zeroed by prep_all each launch

// ---------------------------------------------------------------------------
// helpers
// ---------------------------------------------------------------------------
__device__ __forceinline__ uint32_t smem_u32(const void* p) {
    uint32_t a;
    asm("{ .reg .u64 t; cvta.to.shared.u64 t, %1; cvt.u32.u64 %0, t; }"
        : "=r"(a) : "l"(p));
    return a;
}
__device__ __forceinline__ void cp_async16(uint32_t saddr, const void* gaddr) {
    asm volatile("cp.async.cg.shared.global [%0], [%1], 16;"
                 :: "r"(saddr), "l"(gaddr) : "memory");
}
__device__ __forceinline__ void ldsm4(uint32_t* r, uint32_t a) {
    asm volatile("ldmatrix.sync.aligned.m8n8.x4.shared.b16 {%0,%1,%2,%3}, [%4];"
                 : "=r"(r[0]), "=r"(r[1]), "=r"(r[2]), "=r"(r[3]) : "r"(a));
}
__device__ __forceinline__ void ldsm4t(uint32_t* r, uint32_t a) {
    asm volatile("ldmatrix.sync.aligned.m8n8.x4.trans.shared.b16 {%0,%1,%2,%3}, [%4];"
                 : "=r"(r[0]), "=r"(r[1]), "=r"(r[2]), "=r"(r[3]) : "r"(a));
}
__device__ __forceinline__ void mma16816(float* c, const uint32_t* a, const uint32_t* b) {
    asm volatile(
        "mma.sync.aligned.m16n8k16.row.col.f32.f16.f16.f32 "
        "{%0,%1,%2,%3}, {%4,%5,%6,%7}, {%8,%9}, {%0,%1,%2,%3};"
        : "+f"(c[0]), "+f"(c[1]), "+f"(c[2]), "+f"(c[3])
        : "r"(a[0]), "r"(a[1]), "r"(a[2]), "r"(a[3]), "r"(b[0]), "r"(b[1]));
}

// ---------------------------------------------------------------------------
// prep_all — fused streaming prep (verified R13/R14). g_simflag reset kept.
// ---------------------------------------------------------------------------
__global__ __launch_bounds__(256) void prep_all(
    const float* __restrict__ x, const float* __restrict__ kern,
    const float* __restrict__ key_kernel, float4* __restrict__ out4)
{
    int b = blockIdx.x;
    int tid = threadIdx.x;

    if (b < 4096) {
        __shared__ float t[32][33];
        int m = b >> 8, u0 = ((b >> 4) & 15) * 32, d0 = (b & 15) * 32;
        int tx = tid & 31, ty = tid >> 5;
        const float* src = kern + (size_t)m * D_SZ * U_SZ;
#pragma unroll
        for (int j = 0; j < 4; j++)
            t[ty + 8 * j][tx] = src[(size_t)(d0 + ty + 8 * j) * U_SZ + u0 + tx];
        __syncthreads();
        size_t ob = (size_t)m * U_SZ * D_SZ;
#pragma unroll
        for (int j = 0; j < 4; j++) {
            float v = t[tx][ty + 8 * j];
            g_wh[ob + (size_t)(u0 + ty + 8 * j) * D_SZ + d0 + tx] =
                __float2half_rn(v);
        }
    } else if (b < 5120) {
        uint32_t base = (uint32_t)(b - 4096) * 1024u + tid;
#pragma unroll
        for (int k = 0; k < 4; k++) {
            uint32_t i4 = base + k * 256u;
            float4 v = reinterpret_cast<const float4*>(x)[i4];
            __half2* ph = reinterpret_cast<__half2*>(g_xh) + (size_t)i4 * 2;
            ph[0] = __halves2half2(__float2half_rn(v.x), __float2half_rn(v.y));
            ph[1] = __halves2half2(__float2half_rn(v.z), __float2half_rn(v.w));
        }
    } else if (b < 6144) {
        uint32_t base = (uint32_t)(b - 5120) * 1024u + tid;
#pragma unroll
        for (int k = 0; k < 4; k++)
            out4[base + k * 256u] = make_float4(0.f, 0.f, 0.f, 0.f);
    } else {
        if (tid == 0) g_simflag = 0;          // reset dependency flag
        const float4* kk4 = reinterpret_cast<const float4*>(key_kernel);
#pragma unroll
        for (int j = 0; j < 32; j++) {
            int i = tid + j * 256;
            int row = i >> 4, c4 = (i & 15) * 4;
            float4 v = kk4[i];
            __half2* dst = reinterpret_cast<__half2*>(g_kkh + row * 72 + c4);
            dst[0] = __halves2half2(__float2half_rn(v.x), __float2half_rn(v.y));
            dst[1] = __halves2half2(__float2half_rn(v.z), __float2half_rn(v.w));
        }
    }
}

// ---------------------------------------------------------------------------
// Fused main kernel: 1024 blocks x 512 threads (SAME grid as R14 — no extra
// wave). Blocks 0-127 run keyv for rows [64*bid, 64*bid+64) as a PROLOGUE
// (R15-verified body + publish protocol), then fall through to their normal
// pd work. All blocks defer the sim_sm load to the first fold (it==3), gated
// on g_simflag >= 128 (R15-verified mechanism).
// ---------------------------------------------------------------------------
#define KV_KKH 0                      // half [512][72] = 73728
#define KV_A   73728                  // 3 x (64*144) = 27648  (reused as kvs)
#define KV_KM  (73728 + 27648)        // f32 [16][65] = 4160
#define KV_BS  (KV_KM + 4160)         // f32 [64] = 256

#define ROWB 272         // 128 fp16 cols + 16B pad
#define TILEB (128 * ROWB)          // 34816
#define STAGEB (2 * TILEB)          // 69632
#define SM_BIAS (2 * STAGEB)        // 139264
#define SM_SIM  (SM_BIAS + 16 * 128 * 4)
#define SMEM_TOTAL (SM_SIM + 128 * 16 * 4)   // 155648

__device__ __forceinline__ void issue_loads(
    uint32_t st, int brow0, int bcol0, int g, int tid)
{
    int m = g >> 2;
    int d0 = (g & 3) * 128;
#pragma unroll
    for (int j = 0; j < 8; j++) {
        int idx = tid + j * 512;            // 4096 chunks of 16B
        int tile = idx >> 11;
        int row = (idx >> 4) & 127;
        int seg = idx & 15;
        uint32_t dst = st + tile * TILEB + (uint32_t)(row * ROWB + seg * 16);
        const __half* gp = (tile == 0)
            ? g_xh + (size_t)(brow0 + row) * D_SZ + d0 + seg * 8
            : g_wh + ((size_t)m * U_SZ + bcol0 + row) * D_SZ + d0 + seg * 8;
        cp_async16(dst, gp);
    }
}

__global__ __launch_bounds__(512, 1) void pd_fused(
    const float* __restrict__ biases, const float* __restrict__ key_bias,
    const float* __restrict__ keys_map, float* __restrict__ out)
{
    extern __shared__ __align__(1024) char smem[];
    uint32_t sb = smem_u32(smem);
    int tid = threadIdx.x;
    int lane = tid & 31, warp = tid >> 5;
    int bid = blockIdx.x;

    // ============ keyv prologue on blocks 0-127 (wave 1) ============
    if (bid < 128) {
        int w = warp;
        int b0 = bid * 64;

        float* kmf = reinterpret_cast<float*>(smem + KV_KM);
        float* bs  = reinterpret_cast<float*>(smem + KV_BS);
        if (tid < 64) bs[tid] = key_bias[tid];
        if (tid < 256) {
            kmf[(tid >> 4) * 65 + 4 * (tid & 15) + 0] = keys_map[(tid >> 4) * 64 + 4 * (tid & 15) + 0];
            kmf[(tid >> 4) * 65 + 4 * (tid & 15) + 1] = keys_map[(tid >> 4) * 64 + 4 * (tid & 15) + 1];
            kmf[(tid >> 4) * 65 + 4 * (tid & 15) + 2] = keys_map[(tid >> 4) * 64 + 4 * (tid & 15) + 2];
            kmf[(tid >> 4) * 65 + 4 * (tid & 15) + 3] = keys_map[(tid >> 4) * 64 + 4 * (tid & 15) + 3];
        }

        auto issue_A = [&](uint32_t st, int kc) {
            int row = tid >> 3, seg = tid & 7;
            cp_async16(st + (uint32_t)(row * 144 + seg * 16),
                       g_xh + (size_t)(b0 + row) * D_SZ + kc * 64 + seg * 8);
        };

#pragma unroll
        for (int j = 0; j < 9; j++) {
            int idx = tid + j * 512;
            cp_async16(sb + KV_KKH + (uint32_t)idx * 16, g_kkh + (size_t)idx * 8);
        }
        issue_A(sb + KV_A, 0);
        asm volatile("cp.async.commit_group;" ::: "memory");
        issue_A(sb + KV_A + 9216, 1);
        asm volatile("cp.async.commit_group;" ::: "memory");

        float acc[8][4];
#pragma unroll
        for (int j = 0; j < 8; j++)
#pragma unroll
            for (int i = 0; i < 4; i++) acc[j][i] = 0.f;

        int q = lane >> 3, rr = lane & 7;
        uint32_t aoffb = (uint32_t)((w * 16 + (lane & 15)) * 144 + (lane >> 4) * 16);
        uint32_t boffb = (uint32_t)(KV_KKH + ((q & 1) * 8 + rr) * 144 + ((q >> 1) * 8) * 2);

        for (int kc = 0; kc < 8; kc++) {
            asm volatile("cp.async.wait_group 1;" ::: "memory");
            __syncthreads();
            int k2 = kc + 2;
            if (k2 < 8) issue_A(sb + KV_A + (k2 % 3) * 9216, k2);
            asm volatile("cp.async.commit_group;" ::: "memory");

            if (w < 4) {
                uint32_t ab = sb + KV_A + (kc % 3) * 9216;
#pragma unroll
                for (int ks = 0; ks < 4; ks++) {
                    uint32_t ah[4], bf[4][4];
                    ldsm4(ah, ab + aoffb + ks * 32);
                    uint32_t kb = sb + boffb + (uint32_t)((kc * 64 + ks * 16) * 144);
#pragma unroll
                    for (int p = 0; p < 4; p++)
                        ldsm4t(bf[p], kb + p * 32);
#pragma unroll
                    for (int p = 0; p < 4; p++) {
                        mma16816(acc[2 * p],     ah, &bf[p][0]);
                        mma16816(acc[2 * p + 1], ah, &bf[p][2]);
                    }
                }
            }
        }

        __syncthreads();
        float* kvs = reinterpret_cast<float*>(smem + KV_A);    // [64][68]
        if (w < 4) {
            int r0 = w * 16 + (lane >> 2);
            int c0 = 2 * (lane & 3);
#pragma unroll
            for (int j = 0; j < 8; j++) {
                int col = j * 8 + c0;
                kvs[r0 * 68 + col]           = acc[j][0] + bs[col];
                kvs[r0 * 68 + col + 1]       = acc[j][1] + bs[col + 1];
                kvs[(r0 + 8) * 68 + col]     = acc[j][2] + bs[col];
                kvs[(r0 + 8) * 68 + col + 1] = acc[j][3] + bs[col + 1];
            }
        }
        __syncthreads();

#pragma unroll
        for (int i = 0; i < 2; i++) {
            int task = tid + i * 512;          // 1024 = 64 rows x 16 modes
            int row = task >> 4, mode = task & 15;
            float d2 = 0.f;
#pragma unroll 8
            for (int kk = 0; kk < 64; kk++) {
                float diff = kvs[row * 68 + kk] - kmf[mode * 65 + kk];
                d2 += diff * diff;
            }
            g_sim[(size_t)(b0 + row) * M_SZ + mode] =
                1.0f / (16.0f * (sqrtf(d2) + 1.0f));
        }

        // publish: all g_sim writes -> fence -> barrier -> flag
        __threadfence();
        __syncthreads();
        if (tid == 0) atomicAdd(&g_simflag, 1);
        // fall through to pd work (smem reads all retired by the barrier)
    }

    // ================= pd_mma (verified R14 mainloop) =================
    int split = bid >> 8;                // 0..3
    int rem = bid & 255;
    int bcol0 = (rem & 3) * 128;
    int brow0 = (rem >> 2) * 128;
    int gbase = split * 16;
    int wm = warp & 3, wn = warp >> 2;

    float* bias_sm = reinterpret_cast<float*>(smem + SM_BIAS);
    float* sim_sm  = reinterpret_cast<float*>(smem + SM_SIM);
    if (split == 0)
        for (int i = tid; i < 16 * 128; i += 512)
            bias_sm[i] = biases[(i >> 7) * U_SZ + bcol0 + (i & 127)];

    uint32_t aoff[2], boff[2];
#pragma unroll
    for (int mt = 0; mt < 2; mt++)
        aoff[mt] = (uint32_t)((wm * 32 + mt * 16 + (lane & 15)) * ROWB +
                              ((lane >> 4) * 16));
#pragma unroll
    for (int p = 0; p < 2; p++)
        boff[p] = (uint32_t)((wn * 32 + p * 16 + ((lane >> 4) * 8) + (lane & 7)) * ROWB +
                             (((lane >> 3) & 1) * 16));

    float macc[2][4][4], facc[2][4][4];
#pragma unroll
    for (int mt = 0; mt < 2; mt++)
#pragma unroll
        for (int nt = 0; nt < 4; nt++)
#pragma unroll
            for (int i = 0; i < 4; i++) { macc[mt][nt][i] = 0.f; facc[mt][nt][i] = 0.f; }

    issue_loads(sb, brow0, bcol0, gbase, tid);
    asm volatile("cp.async.commit_group;" ::: "memory");

    for (int it = 0; it < 16; it++) {
        asm volatile("cp.async.wait_group 0;" ::: "memory");
        __syncthreads();
        if (it + 1 < 16) {
            issue_loads(sb + ((it + 1) & 1) * STAGEB, brow0, bcol0,
                        gbase + it + 1, tid);
            asm volatile("cp.async.commit_group;" ::: "memory");
        }

        uint32_t st = sb + (it & 1) * STAGEB;
#pragma unroll
        for (int ks = 0; ks < 8; ks++) {
            uint32_t ah[2][4], bh[2][4];
#pragma unroll
            for (int mt = 0; mt < 2; mt++)
                ldsm4(ah[mt], st + aoff[mt] + ks * 32);
#pragma unroll
            for (int p = 0; p < 2; p++)
                ldsm4(bh[p], st + TILEB + boff[p] + ks * 32);
#pragma unroll
            for (int mt = 0; mt < 2; mt++)
#pragma unroll
                for (int p = 0; p < 2; p++) {
                    mma16816(macc[mt][2 * p],     ah[mt], &bh[p][0]);
                    mma16816(macc[mt][2 * p + 1], ah[mt], &bh[p][2]);
                }
        }

        if (it == 3) {
            // first fold: wait for all 128 keyv carriers, then load sim (L2)
            if (tid == 0) {
                while (atomicAdd(&g_simflag, 0) < 128) __nanosleep(64);
            }
            __syncthreads();
            for (int i = tid; i < 128 * 16; i += 512)
                sim_sm[i] = __ldcg(&g_sim[(brow0 + (i >> 4)) * M_SZ + (i & 15)]);
            __syncthreads();
        }

        if ((it & 3) == 3) {          // mode boundary: fold partials
            int m = (gbase + it) >> 2;
#pragma unroll
            for (int mt = 0; mt < 2; mt++) {
                int ra = wm * 32 + mt * 16 + (lane >> 2);
                float sa = sim_sm[ra * 16 + m];
                float sb_ = sim_sm[(ra + 8) * 16 + m];
#pragma unroll
                for (int nt = 0; nt < 4; nt++) {
                    facc[mt][nt][0] += sa  * macc[mt][nt][0];
                    facc[mt][nt][1] += sa  * macc[mt][nt][1];
                    facc[mt][nt][2] += sb_ * macc[mt][nt][2];
                    facc[mt][nt][3] += sb_ * macc[mt][nt][3];
                    macc[mt][nt][0] = 0.f; macc[mt][nt][1] = 0.f;
                    macc[mt][nt][2] = 0.f; macc[mt][nt][3] = 0.f;
                }
            }
        }
    }

    if (split == 0) {
#pragma unroll
        for (int mt = 0; mt < 2; mt++) {
            int ra = wm * 32 + mt * 16 + (lane >> 2);
            for (int m = 0; m < 16; m++) {
                float sa = sim_sm[ra * 16 + m];
                float sb_ = sim_sm[(ra + 8) * 16 + m];
#pragma unroll
                for (int nt = 0; nt < 4; nt++) {
                    int col = wn * 32 + nt * 8 + 2 * (lane & 3);
                    float b0 = bias_sm[m * 128 + col];
                    float b1 = bias_sm[m * 128 + col + 1];
                    facc[mt][nt][0] += sa * b0;  facc[mt][nt][1] += sa * b1;
                    facc[mt][nt][2] += sb_ * b0; facc[mt][nt][3] += sb_ * b1;
                }
            }
        }
    }

#pragma unroll
    for (int mt = 0; mt < 2; mt++) {
        int ra = brow0 + wm * 32 + mt * 16 + (lane >> 2);
#pragma unroll
        for (int nt = 0; nt < 4; nt++) {
            int col = bcol0 + wn * 32 + nt * 8 + 2 * (lane & 3);
            atomicAdd(&out[(size_t)ra * U_SZ + col],       facc[mt][nt][0]);
            atomicAdd(&out[(size_t)ra * U_SZ + col + 1],   facc[mt][nt][1]);
            atomicAdd(&out[(size_t)(ra + 8) * U_SZ + col],     facc[mt][nt][2]);
            atomicAdd(&out[(size_t)(ra + 8) * U_SZ + col + 1], facc[mt][nt][3]);
        }
    }
}

// ---------------------------------------------------------------------------
extern "C" void kernel_launch(void* const* d_in, const int* in_sizes, int n_in,
                              void* d_out, int out_size)
{
    const float* x          = (const float*)d_in[0];
    const float* key_kernel = (const float*)d_in[1];
    const float* key_bias   = (const float*)d_in[2];
    const float* keys_map   = (const float*)d_in[3];
    const float* kernels    = (const float*)d_in[4];
    const float* biases     = (const float*)d_in[5];
    float* out = (float*)d_out;

    cudaFuncSetAttribute(pd_fused, cudaFuncAttributeMaxDynamicSharedMemorySize,
                         SMEM_TOTAL);

    prep_all<<<6145, 256>>>(x, kernels, key_kernel, (float4*)out);
    pd_fused<<<1024, 512, SMEM_TOTAL>>>(biases, key_bias, keys_map, out);
}

// round 17
// speedup vs baseline: 1.1248x; 1.1248x over previous
#include <cuda_runtime.h>
#include <cuda_fp16.h>
#include <cstdint>

#define B_SZ 8192
#define D_SZ 512
#define U_SZ 512
#define M_SZ 16

// ---------------------------------------------------------------------------
// Scratch (static __device__ — no allocations allowed)
// ---------------------------------------------------------------------------
__device__ float  g_sim[B_SZ * M_SZ];          // sim/16
__device__ __half g_xh[B_SZ * D_SZ];           // [b][d]
__device__ __half g_wh[M_SZ * U_SZ * D_SZ];    // [m][u][d]  (k-major B)
__device__ __half g_kkh[512 * 72];             // key_kernel fp16, padded [512][72]

// ---------------------------------------------------------------------------
// helpers
// ---------------------------------------------------------------------------
__device__ __forceinline__ uint32_t smem_u32(const void* p) {
    uint32_t a;
    asm("{ .reg .u64 t; cvta.to.shared.u64 t, %1; cvt.u32.u64 %0, t; }"
        : "=r"(a) : "l"(p));
    return a;
}
__device__ __forceinline__ void cp_async16(uint32_t saddr, const void* gaddr) {
    asm volatile("cp.async.cg.shared.global [%0], [%1], 16;"
                 :: "r"(saddr), "l"(gaddr) : "memory");
}
__device__ __forceinline__ void ldsm4(uint32_t* r, uint32_t a) {
    asm volatile("ldmatrix.sync.aligned.m8n8.x4.shared.b16 {%0,%1,%2,%3}, [%4];"
                 : "=r"(r[0]), "=r"(r[1]), "=r"(r[2]), "=r"(r[3]) : "r"(a));
}
__device__ __forceinline__ void ldsm4t(uint32_t* r, uint32_t a) {
    asm volatile("ldmatrix.sync.aligned.m8n8.x4.trans.shared.b16 {%0,%1,%2,%3}, [%4];"
                 : "=r"(r[0]), "=r"(r[1]), "=r"(r[2]), "=r"(r[3]) : "r"(a));
}
__device__ __forceinline__ void mma16816(float* c, const uint32_t* a, const uint32_t* b) {
    asm volatile(
        "mma.sync.aligned.m16n8k16.row.col.f32.f16.f16.f32 "
        "{%0,%1,%2,%3}, {%4,%5,%6,%7}, {%8,%9}, {%0,%1,%2,%3};"
        : "+f"(c[0]), "+f"(c[1]), "+f"(c[2]), "+f"(c[3])
        : "r"(a[0]), "r"(a[1]), "r"(a[2]), "r"(a[3]), "r"(b[0]), "r"(b[1]));
}

// ---------------------------------------------------------------------------
// prep_all — fused streaming prep (verified R13/R14). UNCHANGED.
// ---------------------------------------------------------------------------
__global__ __launch_bounds__(256) void prep_all(
    const float* __restrict__ x, const float* __restrict__ kern,
    const float* __restrict__ key_kernel, float4* __restrict__ out4)
{
    int b = blockIdx.x;
    int tid = threadIdx.x;

    if (b < 4096) {
        __shared__ float t[32][33];
        int m = b >> 8, u0 = ((b >> 4) & 15) * 32, d0 = (b & 15) * 32;
        int tx = tid & 31, ty = tid >> 5;
        const float* src = kern + (size_t)m * D_SZ * U_SZ;
#pragma unroll
        for (int j = 0; j < 4; j++)
            t[ty + 8 * j][tx] = src[(size_t)(d0 + ty + 8 * j) * U_SZ + u0 + tx];
        __syncthreads();
        size_t ob = (size_t)m * U_SZ * D_SZ;
#pragma unroll
        for (int j = 0; j < 4; j++) {
            float v = t[tx][ty + 8 * j];
            g_wh[ob + (size_t)(u0 + ty + 8 * j) * D_SZ + d0 + tx] =
                __float2half_rn(v);
        }
    } else if (b < 5120) {
        uint32_t base = (uint32_t)(b - 4096) * 1024u + tid;
#pragma unroll
        for (int k = 0; k < 4; k++) {
            uint32_t i4 = base + k * 256u;
            float4 v = reinterpret_cast<const float4*>(x)[i4];
            __half2* ph = reinterpret_cast<__half2*>(g_xh) + (size_t)i4 * 2;
            ph[0] = __halves2half2(__float2half_rn(v.x), __float2half_rn(v.y));
            ph[1] = __halves2half2(__float2half_rn(v.z), __float2half_rn(v.w));
        }
    } else if (b < 6144) {
        uint32_t base = (uint32_t)(b - 5120) * 1024u + tid;
#pragma unroll
        for (int k = 0; k < 4; k++)
            out4[base + k * 256u] = make_float4(0.f, 0.f, 0.f, 0.f);
    } else {
        const float4* kk4 = reinterpret_cast<const float4*>(key_kernel);
#pragma unroll
        for (int j = 0; j < 32; j++) {
            int i = tid + j * 256;
            int row = i >> 4, c4 = (i & 15) * 4;
            float4 v = kk4[i];
            __half2* dst = reinterpret_cast<__half2*>(g_kkh + row * 72 + c4);
            dst[0] = __halves2half2(__float2half_rn(v.x), __float2half_rn(v.y));
            dst[1] = __halves2half2(__float2half_rn(v.z), __float2half_rn(v.w));
        }
    }
}

// ---------------------------------------------------------------------------
// keyv_sim v2 (verified R13/R14). UNCHANGED.
// ---------------------------------------------------------------------------
#define KV_KKH 0                      // half [512][72] = 73728
#define KV_A   73728                  // 3 x (64*144) = 27648  (reused as kvs)
#define KV_KM  (73728 + 27648)        // f32 [16][65] = 4160
#define KV_BS  (KV_KM + 4160)         // f32 [64] = 256
#define KV_SMEM (KV_BS + 256)         // 105792

__global__ __launch_bounds__(256) void keyv_sim(
    const float* __restrict__ key_bias, const float* __restrict__ keys_map)
{
    extern __shared__ __align__(1024) char sm[];
    uint32_t sb = smem_u32(sm);
    int tid = threadIdx.x;
    int lane = tid & 31, w = tid >> 5;
    int b0 = blockIdx.x * 64;

    float* kmf = reinterpret_cast<float*>(sm + KV_KM);
    float* bs  = reinterpret_cast<float*>(sm + KV_BS);
    if (tid < 64) bs[tid] = key_bias[tid];
    kmf[(tid >> 4) * 65 + 4 * (tid & 15) + 0] = keys_map[(tid >> 4) * 64 + 4 * (tid & 15) + 0];
    kmf[(tid >> 4) * 65 + 4 * (tid & 15) + 1] = keys_map[(tid >> 4) * 64 + 4 * (tid & 15) + 1];
    kmf[(tid >> 4) * 65 + 4 * (tid & 15) + 2] = keys_map[(tid >> 4) * 64 + 4 * (tid & 15) + 2];
    kmf[(tid >> 4) * 65 + 4 * (tid & 15) + 3] = keys_map[(tid >> 4) * 64 + 4 * (tid & 15) + 3];

    auto issue_A = [&](uint32_t st, int kc) {
#pragma unroll
        for (int j = 0; j < 2; j++) {
            int idx = tid + j * 256;
            int row = idx >> 3, seg = idx & 7;
            cp_async16(st + (uint32_t)(row * 144 + seg * 16),
                       g_xh + (size_t)(b0 + row) * D_SZ + kc * 64 + seg * 8);
        }
    };

#pragma unroll
    for (int j = 0; j < 18; j++) {
        int idx = tid + j * 256;
        cp_async16(sb + KV_KKH + (uint32_t)idx * 16, g_kkh + (size_t)idx * 8);
    }
    issue_A(sb + KV_A, 0);
    asm volatile("cp.async.commit_group;" ::: "memory");
    issue_A(sb + KV_A + 9216, 1);
    asm volatile("cp.async.commit_group;" ::: "memory");

    float acc[8][4];
#pragma unroll
    for (int j = 0; j < 8; j++)
#pragma unroll
        for (int i = 0; i < 4; i++) acc[j][i] = 0.f;

    int q = lane >> 3, rr = lane & 7;
    uint32_t aoffb = (uint32_t)((w * 16 + (lane & 15)) * 144 + (lane >> 4) * 16);
    uint32_t boffb = (uint32_t)(KV_KKH + ((q & 1) * 8 + rr) * 144 + ((q >> 1) * 8) * 2);

    for (int kc = 0; kc < 8; kc++) {
        asm volatile("cp.async.wait_group 1;" ::: "memory");
        __syncthreads();
        int k2 = kc + 2;
        if (k2 < 8) issue_A(sb + KV_A + (k2 % 3) * 9216, k2);
        asm volatile("cp.async.commit_group;" ::: "memory");

        if (w < 4) {
            uint32_t ab = sb + KV_A + (kc % 3) * 9216;
#pragma unroll
            for (int ks = 0; ks < 4; ks++) {
                uint32_t ah[4], bf[4][4];
                ldsm4(ah, ab + aoffb + ks * 32);
                uint32_t kb = sb + boffb + (uint32_t)((kc * 64 + ks * 16) * 144);
#pragma unroll
                for (int p = 0; p < 4; p++)
                    ldsm4t(bf[p], kb + p * 32);
#pragma unroll
                for (int p = 0; p < 4; p++) {
                    mma16816(acc[2 * p],     ah, &bf[p][0]);
                    mma16816(acc[2 * p + 1], ah, &bf[p][2]);
                }
            }
        }
    }

    __syncthreads();
    float* kvs = reinterpret_cast<float*>(sm + KV_A);    // [64][68]
    if (w < 4) {
        int r0 = w * 16 + (lane >> 2);
        int c0 = 2 * (lane & 3);
#pragma unroll
        for (int j = 0; j < 8; j++) {
            int col = j * 8 + c0;
            kvs[r0 * 68 + col]           = acc[j][0] + bs[col];
            kvs[r0 * 68 + col + 1]       = acc[j][1] + bs[col + 1];
            kvs[(r0 + 8) * 68 + col]     = acc[j][2] + bs[col];
            kvs[(r0 + 8) * 68 + col + 1] = acc[j][3] + bs[col + 1];
        }
    }
    __syncthreads();

#pragma unroll
    for (int i = 0; i < 4; i++) {
        int task = tid + i * 256;
        int row = task >> 4, mode = task & 15;
        float d2 = 0.f;
#pragma unroll 8
        for (int kk = 0; kk < 64; kk++) {
            float diff = kvs[row * 68 + kk] - kmf[mode * 65 + kk];
            d2 += diff * diff;
        }
        g_sim[(size_t)(b0 + row) * M_SZ + mode] =
            1.0f / (16.0f * (sqrtf(d2) + 1.0f));
    }
}

// ---------------------------------------------------------------------------
// Main HMMA GEMM — verified R14 (BK=128, 2-stage, split-K x4). Two micro-
// tweaks only: table loads moved after first cp.async commit (overlap), and
// bias_sm load gated to split==0 (its only consumer).
// ---------------------------------------------------------------------------
#define ROWB 272         // 128 fp16 cols + 16B pad
#define TILEB (128 * ROWB)          // 34816
#define STAGEB (2 * TILEB)          // 69632
#define SM_BIAS (2 * STAGEB)        // 139264
#define SM_SIM  (SM_BIAS + 16 * 128 * 4)
#define SMEM_TOTAL (SM_SIM + 128 * 16 * 4)   // 155648

__device__ __forceinline__ void issue_loads(
    uint32_t st, int brow0, int bcol0, int g, int tid)
{
    int m = g >> 2;
    int d0 = (g & 3) * 128;
#pragma unroll
    for (int j = 0; j < 8; j++) {
        int idx = tid + j * 512;            // 4096 chunks of 16B
        int tile = idx >> 11;
        int row = (idx >> 4) & 127;
        int seg = idx & 15;
        uint32_t dst = st + tile * TILEB + (uint32_t)(row * ROWB + seg * 16);
        const __half* gp = (tile == 0)
            ? g_xh + (size_t)(brow0 + row) * D_SZ + d0 + seg * 8
            : g_wh + ((size_t)m * U_SZ + bcol0 + row) * D_SZ + d0 + seg * 8;
        cp_async16(dst, gp);
    }
}

__global__ __launch_bounds__(512, 1) void pd_mma(
    const float* __restrict__ biases, float* __restrict__ out)
{
    extern __shared__ __align__(1024) char smem[];
    uint32_t sb = smem_u32(smem);
    int tid = threadIdx.x;
    int lane = tid & 31, warp = tid >> 5;
    int wm = warp & 3, wn = warp >> 2;
    int brow0 = blockIdx.y * 128;
    int bcol0 = blockIdx.x * 128;
    int split = blockIdx.z;
    int gbase = split * 16;                // BK128 iteration base

    // prologue: stage 0 issued FIRST so the DMA overlaps the table loads
    issue_loads(sb, brow0, bcol0, gbase, tid);
    asm volatile("cp.async.commit_group;" ::: "memory");

    float* bias_sm = reinterpret_cast<float*>(smem + SM_BIAS);
    float* sim_sm  = reinterpret_cast<float*>(smem + SM_SIM);
    if (split == 0)
        for (int i = tid; i < 16 * 128; i += 512)
            bias_sm[i] = biases[(i >> 7) * U_SZ + bcol0 + (i & 127)];
    for (int i = tid; i < 128 * 16; i += 512)
        sim_sm[i] = g_sim[(brow0 + (i >> 4)) * M_SZ + (i & 15)];

    uint32_t aoff[2], boff[2];
#pragma unroll
    for (int mt = 0; mt < 2; mt++)
        aoff[mt] = (uint32_t)((wm * 32 + mt * 16 + (lane & 15)) * ROWB +
                              ((lane >> 4) * 16));
#pragma unroll
    for (int p = 0; p < 2; p++)
        boff[p] = (uint32_t)((wn * 32 + p * 16 + ((lane >> 4) * 8) + (lane & 7)) * ROWB +
                             (((lane >> 3) & 1) * 16));

    float macc[2][4][4], facc[2][4][4];
#pragma unroll
    for (int mt = 0; mt < 2; mt++)
#pragma unroll
        for (int nt = 0; nt < 4; nt++)
#pragma unroll
            for (int i = 0; i < 4; i++) { macc[mt][nt][i] = 0.f; facc[mt][nt][i] = 0.f; }

    for (int it = 0; it < 16; it++) {
        // only group `it` is outstanding here
        asm volatile("cp.async.wait_group 0;" ::: "memory");
        // group `it` visible to all threads; all warps done reading buffer
        // (it-1)&1 — safe to overwrite with group it+1. Also orders the
        // sim_sm/bias_sm table stores (it==0) before any reads.
        __syncthreads();
        if (it + 1 < 16) {
            issue_loads(sb + ((it + 1) & 1) * STAGEB, brow0, bcol0,
                        gbase + it + 1, tid);
            asm volatile("cp.async.commit_group;" ::: "memory");
        }

        uint32_t st = sb + (it & 1) * STAGEB;
#pragma unroll
        for (int ks = 0; ks < 8; ks++) {
            uint32_t ah[2][4], bh[2][4];
#pragma unroll
            for (int mt = 0; mt < 2; mt++)
                ldsm4(ah[mt], st + aoff[mt] + ks * 32);
#pragma unroll
            for (int p = 0; p < 2; p++)
                ldsm4(bh[p], st + TILEB + boff[p] + ks * 32);
#pragma unroll
            for (int mt = 0; mt < 2; mt++)
#pragma unroll
                for (int p = 0; p < 2; p++) {
                    mma16816(macc[mt][2 * p],     ah[mt], &bh[p][0]);
                    mma16816(macc[mt][2 * p + 1], ah[mt], &bh[p][2]);
                }
        }

        if ((it & 3) == 3) {          // mode boundary: fold partials
            int m = (gbase + it) >> 2;
#pragma unroll
            for (int mt = 0; mt < 2; mt++) {
                int ra = wm * 32 + mt * 16 + (lane >> 2);
                float sa = sim_sm[ra * 16 + m];
                float sb_ = sim_sm[(ra + 8) * 16 + m];
#pragma unroll
                for (int nt = 0; nt < 4; nt++) {
                    facc[mt][nt][0] += sa  * macc[mt][nt][0];
                    facc[mt][nt][1] += sa  * macc[mt][nt][1];
                    facc[mt][nt][2] += sb_ * macc[mt][nt][2];
                    facc[mt][nt][3] += sb_ * macc[mt][nt][3];
                    macc[mt][nt][0] = 0.f; macc[mt][nt][1] = 0.f;
                    macc[mt][nt][2] = 0.f; macc[mt][nt][3] = 0.f;
                }
            }
        }
    }

    if (split == 0) {
#pragma unroll
        for (int mt = 0; mt < 2; mt++) {
            int ra = wm * 32 + mt * 16 + (lane >> 2);
            for (int m = 0; m < 16; m++) {
                float sa = sim_sm[ra * 16 + m];
                float sb_ = sim_sm[(ra + 8) * 16 + m];
#pragma unroll
                for (int nt = 0; nt < 4; nt++) {
                    int col = wn * 32 + nt * 8 + 2 * (lane & 3);
                    float b0 = bias_sm[m * 128 + col];
                    float b1 = bias_sm[m * 128 + col + 1];
                    facc[mt][nt][0] += sa * b0;  facc[mt][nt][1] += sa * b1;
                    facc[mt][nt][2] += sb_ * b0; facc[mt][nt][3] += sb_ * b1;
                }
            }
        }
    }

#pragma unroll
    for (int mt = 0; mt < 2; mt++) {
        int ra = brow0 + wm * 32 + mt * 16 + (lane >> 2);
#pragma unroll
        for (int nt = 0; nt < 4; nt++) {
            int col = bcol0 + wn * 32 + nt * 8 + 2 * (lane & 3);
            atomicAdd(&out[(size_t)ra * U_SZ + col],       facc[mt][nt][0]);
            atomicAdd(&out[(size_t)ra * U_SZ + col + 1],   facc[mt][nt][1]);
            atomicAdd(&out[(size_t)(ra + 8) * U_SZ + col],     facc[mt][nt][2]);
            atomicAdd(&out[(size_t)(ra + 8) * U_SZ + col + 1], facc[mt][nt][3]);
        }
    }
}

// ---------------------------------------------------------------------------
extern "C" void kernel_launch(void* const* d_in, const int* in_sizes, int n_in,
                              void* d_out, int out_size)
{
    const float* x          = (const float*)d_in[0];
    const float* key_kernel = (const float*)d_in[1];
    const float* key_bias   = (const float*)d_in[2];
    const float* keys_map   = (const float*)d_in[3];
    const float* kernels    = (const float*)d_in[4];
    const float* biases     = (const float*)d_in[5];
    float* out = (float*)d_out;

    cudaFuncSetAttribute(pd_mma, cudaFuncAttributeMaxDynamicSharedMemorySize,
                         SMEM_TOTAL);
    cudaFuncSetAttribute(keyv_sim, cudaFuncAttributeMaxDynamicSharedMemorySize,
                         KV_SMEM);

    prep_all<<<6145, 256>>>(x, kernels, key_kernel, (float4*)out);
    keyv_sim<<<B_SZ / 64, 256, KV_SMEM>>>(key_bias, keys_map);

    dim3 grid(U_SZ / 128, B_SZ / 128, 4);
    pd_mma<<<grid, 512, SMEM_TOTAL>>>(biases, out);
}